// round 16
// baseline (speedup 1.0000x reference)
#include <cuda_runtime.h>
#include <cuda_bf16.h>
#include <math.h>
#include <stdint.h>

#define D    512
#define NTOK 32768
#define KCB  8192
#define MT   128              // rows per CTA
#define NT   128              // codes per n-iter
#define KC   128              // k per chunk (two 64-k sub-tiles)
#define KQ   4                // codebook quarters (work-split)
#define KQ_CODES (KCB / KQ)   // 2048
#define NITER ((KQ_CODES / NT) * (D / KC))   // 16 * 4 = 64
#define A_BYTES (MT * D * 2)            // 131072
#define B_STAGE (NT * KC * 2)           // 32768
#define NSTAGE 3
#define SMEM_SZ (A_BYTES + NSTAGE * B_STAGE) // 229376 (224KB)

// ---------------- device globals ----------------
__device__ __nv_bfloat16 g_zh[(size_t)NTOK * D];
__device__ __nv_bfloat16 g_ch[(size_t)KCB * D];
__device__ float g_zsq[NTOK];
__device__ float g_csq[KCB];
__device__ float g_dmin[NTOK];
__device__ float g_H[NTOK];
// per (kq, row) partials: S, T, top-3 noisy candidates
__device__ float g_ps[KQ * NTOK], g_pt[KQ * NTOK];
__device__ float g_pv0[KQ * NTOK], g_pv1[KQ * NTOK], g_pv2[KQ * NTOK];
__device__ int   g_pi0[KQ * NTOK], g_pi1[KQ * NTOK], g_pi2[KQ * NTOK];

// ---------------- helpers ----------------
__device__ __forceinline__ uint32_t smem_u32(const void* p) {
    uint32_t a;
    asm("{ .reg .u64 t; cvta.to.shared.u64 t, %1; cvt.u32.u64 %0, t; }" : "=r"(a) : "l"(p));
    return a;
}
__device__ __forceinline__ void cp16(uint32_t s, const void* g) {
    asm volatile("cp.async.cg.shared.global [%0], [%1], 16;" :: "r"(s), "l"(g));
}
#define CP_COMMIT()  asm volatile("cp.async.commit_group;" ::: "memory")
#define CP_WAIT(n)   asm volatile("cp.async.wait_group %0;" :: "n"(n) : "memory")

__device__ __forceinline__ void ldsm4(uint32_t& r0, uint32_t& r1, uint32_t& r2, uint32_t& r3, uint32_t a) {
    asm volatile("ldmatrix.sync.aligned.m8n8.x4.shared.b16 {%0,%1,%2,%3}, [%4];"
                 : "=r"(r0), "=r"(r1), "=r"(r2), "=r"(r3) : "r"(a));
}
__device__ __forceinline__ void mma16816(float* c, uint32_t a0, uint32_t a1, uint32_t a2, uint32_t a3,
                                         uint32_t b0, uint32_t b1) {
    asm volatile("mma.sync.aligned.m16n8k16.row.col.f32.bf16.bf16.f32 "
                 "{%0,%1,%2,%3},{%4,%5,%6,%7},{%8,%9},{%0,%1,%2,%3};"
                 : "+f"(c[0]), "+f"(c[1]), "+f"(c[2]), "+f"(c[3])
                 : "r"(a0), "r"(a1), "r"(a2), "r"(a3), "r"(b0), "r"(b1));
}
__device__ __forceinline__ float sqrt_apx(float x) {
    float r; asm("sqrt.approx.f32 %0, %1;" : "=f"(r) : "f"(x)); return r;
}

// ---------------- fused split: fp32 -> bf16 + row sumsq ----------------
__global__ void split_kernel(const float* __restrict__ z, const float* __restrict__ cb,
                             int N, int K) {
    int w = (blockIdx.x * blockDim.x + threadIdx.x) >> 5;
    int lane = threadIdx.x & 31;
    if (w >= N + K) return;
    int which = (w >= N);
    int row = which ? (w - N) : w;
    const float* src = which ? cb : z;
    __nv_bfloat16* dst = which ? g_ch : g_zh;
    const float4* p = (const float4*)(src + (size_t)row * D);
    float acc = 0.f;
#pragma unroll
    for (int i = 0; i < 4; ++i) {
        float4 v = p[lane + i * 32];
        acc += v.x * v.x + v.y * v.y + v.z * v.z + v.w * v.w;
        __nv_bfloat162 h01 = __floats2bfloat162_rn(v.x, v.y);
        __nv_bfloat162 h23 = __floats2bfloat162_rn(v.z, v.w);
        uint2 u; u.x = *(uint32_t*)&h01; u.y = *(uint32_t*)&h23;
        *(uint2*)(dst + (size_t)row * D + (lane + i * 32) * 4) = u;
    }
#pragma unroll
    for (int off = 16; off; off >>= 1) acc += __shfl_down_sync(0xffffffffu, acc, off);
    if (lane == 0) { if (which) g_csq[row] = acc; else g_zsq[row] = acc; }
}

// ---------------- B chunk loader (32KB = two 64-k sub-tiles) ----------------
__device__ __forceinline__ void load_b(uint32_t sb, int iter, int buf, int tid, int code_base) {
    int nt = iter >> 2, kc2 = iter & 3;
    uint32_t st = sb + A_BYTES + (uint32_t)buf * B_STAGE;
    const __nv_bfloat16* bh = g_ch + (size_t)(code_base + nt * NT) * D + kc2 * KC;
#pragma unroll
    for (int i = 0; i < 8; ++i) {
        int q = tid + i * 256;
        int h = q >> 10, u = q & 1023, r = u >> 3, c16 = u & 7;
        uint32_t off = (uint32_t)(h * 16384 + r * 128 + ((c16 * 16) ^ ((r & 7) << 4)));
        cp16(st + off, bh + (size_t)r * D + h * 64 + c16 * 8);
    }
}

// ---------------- main bf16 HMMA GEMM + deferred (hidden) epilogue ----------------
__global__ void __launch_bounds__(256, 1) gemm_kernel() {
    extern __shared__ __align__(1024) char sm[];
    uint32_t sb = smem_u32(sm);
    int tid = threadIdx.x, lane = tid & 31, wid = tid >> 5;
    int wm = wid & 3, wn = wid >> 2;          // warp grid 4(M) x 2(N); warp tile 32x64
    int mt = blockIdx.x & 255;
    int kq = blockIdx.x >> 8;
    int n0 = mt * MT;
    int code_base = kq * KQ_CODES;

    // ---- load A (z bf16, 128x512) resident, 8 swizzled chunks of [128][64]
    {
        const __nv_bfloat16* zb = g_zh + (size_t)n0 * D;
#pragma unroll
        for (int i = 0; i < 32; ++i) {
            int q = tid + i * 256;
            int kc = q >> 10, u = q & 1023, r = u >> 3, c16 = u & 7;
            uint32_t so = sb + (uint32_t)(kc * 16384 + r * 128 + ((c16 * 16) ^ ((r & 7) << 4)));
            cp16(so, zb + (size_t)r * D + kc * 64 + c16 * 8);
        }
    }
    load_b(sb, 0, 0, tid, code_base); CP_COMMIT();
    load_b(sb, 1, 1, tid, code_base); CP_COMMIT();

    float ss[4], tt[4], zs[4];
    float tv0[4], tv1[4], tv2[4];             // scalar arrays, constant-indexed only
    int   ti0[4], ti1[4], ti2[4];
#pragma unroll
    for (int s = 0; s < 4; ++s) {
        ss[s] = 0.f; tt[s] = 0.f;
        tv0[s] = tv1[s] = tv2[s] = 1e30f;
        ti0[s] = ti1[s] = ti2[s] = 0;
        int row = n0 + wm * 32 + (s >> 1) * 16 + (lane >> 2) + (s & 1) * 8;
        zs[s] = g_zsq[row];
    }

    float accA[2][8][4], accB[2][8][4];
    int laneA_r[2], laneB_r[4];
#pragma unroll
    for (int m = 0; m < 2; ++m)
        laneA_r[m] = wm * 32 + m * 16 + (lane & 7) + ((lane >> 3) & 1) * 8;
#pragma unroll
    for (int p = 0; p < 4; ++p)
        laneB_r[p] = wn * 64 + (p * 2 + ((lane >> 4) & 1)) * 8 + (lane & 7);
    int byteA = ((lane >> 4) & 1) * 16;
    int byteB = ((lane >> 3) & 1) * 16;

    int gi = 0, buf = 0, pbuf = 2;            // 3-stage ring

    // epilogue fragment: 8 codes (n-frag j) of a finished tile in pacc
    auto epi_frag = [&](float (&pacc)[2][8][4], int j, int ecb) {
        float c0 = __ldg(g_csq + ecb + j * 8);
        float c1 = __ldg(g_csq + ecb + j * 8 + 1);
#pragma unroll
        for (int m = 0; m < 2; ++m)
#pragma unroll
            for (int h = 0; h < 2; ++h)
#pragma unroll
                for (int q = 0; q < 2; ++q) {
                    int s = m * 2 + h;
                    float dot = pacc[m][j][h * 2 + q];
                    int code = ecb + j * 8 + q;
                    float d2 = fmaf(-2.f, dot, zs[s] + (q ? c1 : c0));
                    d2 = fmaxf(d2, 1e-6f);
                    float d = sqrt_apx(d2);
                    float e = __expf(-d);           // max-free, in fp32 range
                    ss[s] += e;
                    tt[s] = fmaf(e, d, tt[s]);
                    if (d2 < tv2[s]) {              // constant-index insert tree
                        if (d2 < tv1[s]) {
                            tv2[s] = tv1[s]; ti2[s] = ti1[s];
                            if (d2 < tv0[s]) {
                                tv1[s] = tv0[s]; ti1[s] = ti0[s];
                                tv0[s] = d2; ti0[s] = code;
                            } else { tv1[s] = d2; ti1[s] = code; }
                        } else { tv2[s] = d2; ti2[s] = code; }
                    }
                }
    };

    // 4 chunk-iterations for one n-tile into cacc; during kc2==0, interleave
    // the deferred epilogue of the PREVIOUS tile (pacc) at j-step granularity.
    auto run4 = [&](float (&cacc)[2][8][4], float (&pacc)[2][8][4], int tile, int doEpi) {
        int ecb = code_base + (tile - 1) * NT + wn * 64 + (lane & 3) * 2;
        for (int kc2 = 0; kc2 < 4; ++kc2) {
            CP_WAIT(1);
            __syncthreads();
            if (gi + 2 < NITER) { load_b(sb, gi + 2, pbuf, tid, code_base); CP_COMMIT(); }
            uint32_t bbase = sb + A_BYTES + (uint32_t)buf * B_STAGE;

            if (kc2 == 0) {
#pragma unroll
                for (int m = 0; m < 2; ++m)
#pragma unroll
                    for (int n = 0; n < 8; ++n)
#pragma unroll
                        for (int q = 0; q < 4; ++q) cacc[m][n][q] = 0.f;
            }
            int de = doEpi && (kc2 == 0);

#pragma unroll
            for (int j = 0; j < 8; ++j) {
                int half = j >> 2, jj = j & 3;
                uint32_t abase = sb + (uint32_t)(kc2 * 2 + half) * 16384;
                uint32_t bb = bbase + (uint32_t)half * 16384;
                uint32_t a[2][4];
#pragma unroll
                for (int m = 0; m < 2; ++m) {
                    int r = laneA_r[m];
                    uint32_t ad = abase + (uint32_t)(r * 128 + ((jj * 32 + byteA) ^ ((r & 7) << 4)));
                    ldsm4(a[m][0], a[m][1], a[m][2], a[m][3], ad);
                }
                uint32_t bh[8][2];
#pragma unroll
                for (int p = 0; p < 4; ++p) {
                    int r = laneB_r[p];
                    uint32_t off = (uint32_t)(r * 128 + ((jj * 32 + byteB) ^ ((r & 7) << 4)));
                    ldsm4(bh[2 * p][0], bh[2 * p][1], bh[2 * p + 1][0], bh[2 * p + 1][1], bb + off);
                }
#pragma unroll
                for (int m = 0; m < 2; ++m)
#pragma unroll
                    for (int n = 0; n < 8; ++n)
                        mma16816(cacc[m][n], a[m][0], a[m][1], a[m][2], a[m][3], bh[n][0], bh[n][1]);
                if (de) epi_frag(pacc, j, ecb);
            }

            ++gi;
            buf = (buf == 2) ? 0 : buf + 1;
            pbuf = (pbuf == 2) ? 0 : pbuf + 1;
        }
    };

    for (int p = 0; p < 8; ++p) {
        run4(accA, accB, 2 * p, p > 0);
        run4(accB, accA, 2 * p + 1, 1);
    }
    // final epilogue: tile 15 lives in accB
    {
        int ecb = code_base + 15 * NT + wn * 64 + (lane & 3) * 2;
#pragma unroll
        for (int j = 0; j < 8; ++j) epi_frag(accB, j, ecb);
    }

    // ---- merge 8 warp-partials per row via smem (record = 8 words)
    __syncthreads();
    float* msm = (float*)(sm + A_BYTES);
    int*   mim = (int*)msm;
    const int REC = 8;
#pragma unroll
    for (int s = 0; s < 4; ++s) {
        int row_local = wm * 32 + (s >> 1) * 16 + (lane >> 2) + (s & 1) * 8;
        int base = (row_local * 8 + wn * 4 + (lane & 3)) * REC;
        msm[base + 0] = ss[s]; msm[base + 1] = tt[s];
        msm[base + 2] = tv0[s]; msm[base + 3] = tv1[s]; msm[base + 4] = tv2[s];
        mim[base + 5] = ti0[s]; mim[base + 6] = ti1[s]; mim[base + 7] = ti2[s];
    }
    __syncthreads();
    if (tid < 128) {
        int row = tid;
        float S = 0.f, T = 0.f;
        float bv0 = 1e30f, bv1 = 1e30f, bv2 = 1e30f;
        int bi0 = 0, bi1 = 0, bi2 = 0;
#pragma unroll
        for (int j = 0; j < 8; ++j) {
            int base = (row * 8 + j) * REC;
            S += msm[base + 0];
            T += msm[base + 1];
#pragma unroll
            for (int k = 0; k < 3; ++k) {
                float v = msm[base + 2 + k];
                int   ix = mim[base + 5 + k];
                if (v < bv2) {
                    if (v < bv1) {
                        bv2 = bv1; bi2 = bi1;
                        if (v < bv0) { bv1 = bv0; bi1 = bi0; bv0 = v; bi0 = ix; }
                        else         { bv1 = v;  bi1 = ix; }
                    } else { bv2 = v; bi2 = ix; }
                }
            }
        }
        int gp = kq * NTOK + n0 + row;
        g_ps[gp] = S; g_pt[gp] = T;
        g_pv0[gp] = bv0; g_pv1[gp] = bv1; g_pv2[gp] = bv2;
        g_pi0[gp] = bi0; g_pi1[gp] = bi1; g_pi2[gp] = bi2;
    }
}

// ---------------- merge + exact rescore (early-exit) + outputs ----------------
__global__ void mergeout_kernel(const float* __restrict__ z, const float* __restrict__ cb,
                                const float* __restrict__ yb, const float* __restrict__ et,
                                float* __restrict__ out, int N) {
    int warp = (blockIdx.x * blockDim.x + threadIdx.x) >> 5;
    int lane = threadIdx.x & 31;
    if (warp >= N) return;

    float S = 0.f, T = 0.f;
    float bv0 = 1e30f, bv1 = 1e30f, bv2 = 1e30f, bv3 = 1e30f;
    int bi0 = 0, bi1 = 0, bi2 = 0, bi3 = 0;
#pragma unroll
    for (int j = 0; j < KQ; ++j) {
        int gp = j * NTOK + warp;
        S += g_ps[gp];
        T += g_pt[gp];
        float vs[3] = {g_pv0[gp], g_pv1[gp], g_pv2[gp]};
        int   is[3] = {g_pi0[gp], g_pi1[gp], g_pi2[gp]};
#pragma unroll
        for (int k = 0; k < 3; ++k) {
            float v = vs[k]; int ix = is[k];
            if (v < bv3) {                                 // constant-index top-4 tree
                if (v < bv1) {
                    bv3 = bv2; bi3 = bi2;
                    bv2 = bv1; bi2 = bi1;
                    if (v < bv0) { bv1 = bv0; bi1 = bi0; bv0 = v; bi0 = ix; }
                    else         { bv1 = v;  bi1 = ix; }
                } else {
                    if (v < bv2) { bv3 = bv2; bi3 = bi2; bv2 = v; bi2 = ix; }
                    else         { bv3 = v;  bi3 = ix; }
                }
            }
        }
    }

    float4 zv[4];
    const float4* zr = (const float4*)(z + (size_t)warp * D);
#pragma unroll
    for (int i = 0; i < 4; ++i) zv[i] = zr[lane + i * 32];
    float zsq = g_zsq[warp];

    // exact rescore with early exit: noisy d2 error sigma ~0.06, cut at 8 sigma
    float cut = bv0 + 0.5f;
    int cand[4] = {bi0, bi1, bi2, bi3};
    float cnv[4] = {bv0, bv1, bv2, bv3};
    float best = 1e30f; int bidx = 0x7fffffff;
#pragma unroll
    for (int c = 0; c < 4; ++c) {
        if (c > 0 && cnv[c] > cut) break;      // warp-uniform (sorted)
        int idx = cand[c];
        const float4* cr = (const float4*)(cb + (size_t)idx * D);
        float dot = 0.f;
#pragma unroll
        for (int i = 0; i < 4; ++i) {
            float4 cv = cr[lane + i * 32];
            dot += zv[i].x * cv.x + zv[i].y * cv.y + zv[i].z * cv.z + zv[i].w * cv.w;
        }
#pragma unroll
        for (int off = 16; off; off >>= 1) dot += __shfl_xor_sync(0xffffffffu, dot, off);
        float d2 = fmaxf(zsq + g_csq[idx] - 2.f * dot, 0.f);
        if (d2 < best || (d2 == best && idx < bidx)) { best = d2; bidx = idx; }
    }

    // winner row is L1-hot from the rescore loop: write quantized + deviation
    const float4* crow = (const float4*)(cb + (size_t)bidx * D);
    const float4* yrow = (const float4*)(yb + (size_t)warp * D);
    float4*       qrow = (float4*)(out + (size_t)warp * D);
    float dacc = 0.f;
#pragma unroll
    for (int i = 0; i < 4; ++i) {
        float4 cv = crow[lane + i * 32];
        float4 yv = yrow[lane + i * 32];
        qrow[lane + i * 32] = cv;
        float dx = cv.x - yv.x, dy = cv.y - yv.y, dz = cv.z - yv.z, dw = cv.w - yv.w;
        dacc += dx * dx + dy * dy + dz * dz + dw * dw;
    }
#pragma unroll
    for (int off = 16; off; off >>= 1) dacc += __shfl_down_sync(0xffffffffu, dacc, off);
    if (lane == 0) {
        g_dmin[warp] = sqrtf(best);
        g_H[warp]    = __logf(S) + T / S;     // max-free identity
        float dev = sqrtf(dacc);
        out[(size_t)N * D + N + warp] = et[warp] + (dev > 0.01f ? 1.0f : 0.0f);
    }
}

// ---------------- loss reduce + broadcast into output ----------------
__global__ void loss_kernel(float* __restrict__ out, int N) {
    __shared__ float sd[1024], sh[1024];
    int t = threadIdx.x;
    float a = 0.f, b = 0.f;
    const float4* pd = (const float4*)g_dmin;
    const float4* ph = (const float4*)g_H;
    for (int i = t; i < N / 4; i += 1024) {
        float4 vd = pd[i], vh = ph[i];
        a += vd.x + vd.y + vd.z + vd.w;
        b += vh.x + vh.y + vh.z + vh.w;
    }
    sd[t] = a; sh[t] = b;
    __syncthreads();
    for (int off = 512; off; off >>= 1) {
        if (t < off) { sd[t] += sd[t + off]; sh[t] += sh[t + off]; }
        __syncthreads();
    }
    if (t == 0) sd[0] = sd[0] / (float)N + 0.1f * sh[0] / (float)N;
    __syncthreads();
    float loss = sd[0];
    for (int i = t; i < N; i += 1024) out[(size_t)N * D + i] = loss;
}

extern "C" void kernel_launch(void* const* d_in, const int* in_sizes, int n_in,
                              void* d_out, int out_size) {
    const float* z  = (const float*)d_in[0];
    const float* yb = (const float*)d_in[1];
    const float* et = (const float*)d_in[2];
    const float* cb = (const float*)d_in[3];
    int N = in_sizes[0] / D;
    int K = in_sizes[3] / D;
    float* out = (float*)d_out;

    cudaFuncSetAttribute(gemm_kernel, cudaFuncAttributeMaxDynamicSharedMemorySize, SMEM_SZ);

    split_kernel<<<(N + K + 7) / 8, 256>>>(z, cb, N, K);
    gemm_kernel<<<256 * KQ, 256, SMEM_SZ>>>();
    mergeout_kernel<<<(N + 7) / 8, 256>>>(z, cb, yb, et, out, N);
    loss_kernel<<<1, 1024>>>(out, N);
}

// round 17
// speedup vs baseline: 1.0293x; 1.0293x over previous
#include <cuda_runtime.h>
#include <cuda_bf16.h>
#include <math.h>
#include <stdint.h>

#define D    512
#define NTOK 32768
#define KCB  8192
#define MT   128              // rows per CTA
#define NT   128              // codes per n-iter
#define KC   128              // k per chunk (two 64-k sub-tiles)
#define KQ   4                // codebook quarters (work-split)
#define KQ_CODES (KCB / KQ)   // 2048
#define NITER ((KQ_CODES / NT) * (D / KC))   // 16 * 4 = 64
#define A_BYTES (MT * D * 2)            // 131072
#define B_STAGE (NT * KC * 2)           // 32768
#define NSTAGE 3
#define SMEM_SZ (A_BYTES + NSTAGE * B_STAGE) // 229376 (224KB)

#define LR_BLOCKS 64          // loss reduce blocks

// ---------------- device globals ----------------
__device__ __nv_bfloat16 g_zh[(size_t)NTOK * D];
__device__ __nv_bfloat16 g_ch[(size_t)KCB * D];
__device__ float g_zsq[NTOK];
__device__ float g_csq[KCB];
__device__ float g_dmin[NTOK];
__device__ float g_H[NTOK];
__device__ float g_pr[LR_BLOCKS], g_phh[LR_BLOCKS];
// per (kq, row) partials: S, T, top-3 noisy candidates
__device__ float g_ps[KQ * NTOK], g_pt[KQ * NTOK];
__device__ float g_pv0[KQ * NTOK], g_pv1[KQ * NTOK], g_pv2[KQ * NTOK];
__device__ int   g_pi0[KQ * NTOK], g_pi1[KQ * NTOK], g_pi2[KQ * NTOK];

// ---------------- helpers ----------------
__device__ __forceinline__ uint32_t smem_u32(const void* p) {
    uint32_t a;
    asm("{ .reg .u64 t; cvta.to.shared.u64 t, %1; cvt.u32.u64 %0, t; }" : "=r"(a) : "l"(p));
    return a;
}
__device__ __forceinline__ void cp16(uint32_t s, const void* g) {
    asm volatile("cp.async.cg.shared.global [%0], [%1], 16;" :: "r"(s), "l"(g));
}
#define CP_COMMIT()  asm volatile("cp.async.commit_group;" ::: "memory")
#define CP_WAIT(n)   asm volatile("cp.async.wait_group %0;" :: "n"(n) : "memory")

__device__ __forceinline__ void ldsm4(uint32_t& r0, uint32_t& r1, uint32_t& r2, uint32_t& r3, uint32_t a) {
    asm volatile("ldmatrix.sync.aligned.m8n8.x4.shared.b16 {%0,%1,%2,%3}, [%4];"
                 : "=r"(r0), "=r"(r1), "=r"(r2), "=r"(r3) : "r"(a));
}
__device__ __forceinline__ void mma16816(float* c, uint32_t a0, uint32_t a1, uint32_t a2, uint32_t a3,
                                         uint32_t b0, uint32_t b1) {
    asm volatile("mma.sync.aligned.m16n8k16.row.col.f32.bf16.bf16.f32 "
                 "{%0,%1,%2,%3},{%4,%5,%6,%7},{%8,%9},{%0,%1,%2,%3};"
                 : "+f"(c[0]), "+f"(c[1]), "+f"(c[2]), "+f"(c[3])
                 : "r"(a0), "r"(a1), "r"(a2), "r"(a3), "r"(b0), "r"(b1));
}
__device__ __forceinline__ float sqrt_apx(float x) {
    float r; asm("sqrt.approx.f32 %0, %1;" : "=f"(r) : "f"(x)); return r;
}

// ---------------- fused split: fp32 -> bf16 + row sumsq ----------------
__global__ void split_kernel(const float* __restrict__ z, const float* __restrict__ cb,
                             int N, int K) {
    int w = (blockIdx.x * blockDim.x + threadIdx.x) >> 5;
    int lane = threadIdx.x & 31;
    if (w >= N + K) return;
    int which = (w >= N);
    int row = which ? (w - N) : w;
    const float* src = which ? cb : z;
    __nv_bfloat16* dst = which ? g_ch : g_zh;
    const float4* p = (const float4*)(src + (size_t)row * D);
    float acc = 0.f;
#pragma unroll
    for (int i = 0; i < 4; ++i) {
        float4 v = p[lane + i * 32];
        acc += v.x * v.x + v.y * v.y + v.z * v.z + v.w * v.w;
        __nv_bfloat162 h01 = __floats2bfloat162_rn(v.x, v.y);
        __nv_bfloat162 h23 = __floats2bfloat162_rn(v.z, v.w);
        uint2 u; u.x = *(uint32_t*)&h01; u.y = *(uint32_t*)&h23;
        *(uint2*)(dst + (size_t)row * D + (lane + i * 32) * 4) = u;
    }
#pragma unroll
    for (int off = 16; off; off >>= 1) acc += __shfl_down_sync(0xffffffffu, acc, off);
    if (lane == 0) { if (which) g_csq[row] = acc; else g_zsq[row] = acc; }
}

// ---------------- B chunk loader (32KB = two 64-k sub-tiles) ----------------
__device__ __forceinline__ void load_b(uint32_t sb, int iter, int buf, int tid, int code_base) {
    int nt = iter >> 2, kc2 = iter & 3;
    uint32_t st = sb + A_BYTES + (uint32_t)buf * B_STAGE;
    const __nv_bfloat16* bh = g_ch + (size_t)(code_base + nt * NT) * D + kc2 * KC;
#pragma unroll
    for (int i = 0; i < 8; ++i) {
        int q = tid + i * 256;
        int h = q >> 10, u = q & 1023, r = u >> 3, c16 = u & 7;
        uint32_t off = (uint32_t)(h * 16384 + r * 128 + ((c16 * 16) ^ ((r & 7) << 4)));
        cp16(st + off, bh + (size_t)r * D + h * 64 + c16 * 8);
    }
}

// ---------------- main bf16 HMMA GEMM + fused max-free epilogue ----------------
__global__ void __launch_bounds__(256, 1) gemm_kernel() {
    extern __shared__ __align__(1024) char sm[];
    uint32_t sb = smem_u32(sm);
    int tid = threadIdx.x, lane = tid & 31, wid = tid >> 5;
    int wm = wid & 3, wn = wid >> 2;          // warp grid 4(M) x 2(N); warp tile 32x64
    int mt = blockIdx.x & 255;
    int kq = blockIdx.x >> 8;
    int n0 = mt * MT;
    int code_base = kq * KQ_CODES;

    // ---- load A (z bf16, 128x512) resident, 8 swizzled chunks of [128][64]
    {
        const __nv_bfloat16* zb = g_zh + (size_t)n0 * D;
#pragma unroll
        for (int i = 0; i < 32; ++i) {
            int q = tid + i * 256;
            int kc = q >> 10, u = q & 1023, r = u >> 3, c16 = u & 7;
            uint32_t so = sb + (uint32_t)(kc * 16384 + r * 128 + ((c16 * 16) ^ ((r & 7) << 4)));
            cp16(so, zb + (size_t)r * D + kc * 64 + c16 * 8);
        }
    }
    load_b(sb, 0, 0, tid, code_base); CP_COMMIT();
    load_b(sb, 1, 1, tid, code_base); CP_COMMIT();

    float ss[4], tt[4], zs[4];
    float tv0[4], tv1[4], tv2[4];             // scalar arrays, constant-indexed only
    int   ti0[4], ti1[4], ti2[4];
#pragma unroll
    for (int s = 0; s < 4; ++s) {
        ss[s] = 0.f; tt[s] = 0.f;
        tv0[s] = tv1[s] = tv2[s] = 1e30f;
        ti0[s] = ti1[s] = ti2[s] = 0;
        int row = n0 + wm * 32 + (s >> 1) * 16 + (lane >> 2) + (s & 1) * 8;
        zs[s] = g_zsq[row];
    }

    float acc[2][8][4];
    int laneA_r[2], laneB_r[4];
#pragma unroll
    for (int m = 0; m < 2; ++m)
        laneA_r[m] = wm * 32 + m * 16 + (lane & 7) + ((lane >> 3) & 1) * 8;
#pragma unroll
    for (int p = 0; p < 4; ++p)
        laneB_r[p] = wn * 64 + (p * 2 + ((lane >> 4) & 1)) * 8 + (lane & 7);
    int byteA = ((lane >> 4) & 1) * 16;
    int byteB = ((lane >> 3) & 1) * 16;

    int buf = 0, pbuf = 2;                    // 3-stage ring
    for (int it = 0; it < NITER; ++it) {
        CP_WAIT(1);
        __syncthreads();
        if (it + 2 < NITER) {
            load_b(sb, it + 2, pbuf, tid, code_base); CP_COMMIT();
        }

        int kc2 = it & 3;
        uint32_t bbase = sb + A_BYTES + (uint32_t)buf * B_STAGE;

        if (kc2 == 0) {
#pragma unroll
            for (int m = 0; m < 2; ++m)
#pragma unroll
                for (int n = 0; n < 8; ++n)
#pragma unroll
                    for (int q = 0; q < 4; ++q) acc[m][n][q] = 0.f;
        }

#pragma unroll
        for (int j = 0; j < 8; ++j) {
            int half = j >> 2, jj = j & 3;
            uint32_t abase = sb + (uint32_t)(kc2 * 2 + half) * 16384;
            uint32_t bb = bbase + (uint32_t)half * 16384;
            uint32_t a[2][4];
#pragma unroll
            for (int m = 0; m < 2; ++m) {
                int r = laneA_r[m];
                uint32_t ad = abase + (uint32_t)(r * 128 + ((jj * 32 + byteA) ^ ((r & 7) << 4)));
                ldsm4(a[m][0], a[m][1], a[m][2], a[m][3], ad);
            }
            uint32_t bh[8][2];
#pragma unroll
            for (int p = 0; p < 4; ++p) {
                int r = laneB_r[p];
                uint32_t off = (uint32_t)(r * 128 + ((jj * 32 + byteB) ^ ((r & 7) << 4)));
                ldsm4(bh[2 * p][0], bh[2 * p][1], bh[2 * p + 1][0], bh[2 * p + 1][1], bb + off);
            }
#pragma unroll
            for (int m = 0; m < 2; ++m)
#pragma unroll
                for (int n = 0; n < 8; ++n)
                    mma16816(acc[m][n], a[m][0], a[m][1], a[m][2], a[m][3], bh[n][0], bh[n][1]);
        }

        if (kc2 == 3) {                       // fused max-free epilogue, 128-code tile
            int nt = it >> 2;
            int colbase = code_base + nt * NT + wn * 64 + (lane & 3) * 2;
            float csv[16];
#pragma unroll
            for (int n = 0; n < 8; ++n) {
                csv[2 * n]     = __ldg(g_csq + colbase + n * 8);
                csv[2 * n + 1] = __ldg(g_csq + colbase + n * 8 + 1);
            }
#pragma unroll
            for (int m = 0; m < 2; ++m)
#pragma unroll
                for (int n = 0; n < 8; ++n)
#pragma unroll
                    for (int h = 0; h < 2; ++h)
#pragma unroll
                        for (int q = 0; q < 2; ++q) {
                            int s = m * 2 + h;
                            float dot = acc[m][n][h * 2 + q];
                            int code = colbase + n * 8 + q;
                            float d2 = fmaf(-2.f, dot, zs[s] + csv[2 * n + q]);
                            d2 = fmaxf(d2, 1e-6f);
                            float d = sqrt_apx(d2);
                            float e = __expf(-d);           // max-free, in fp32 range
                            ss[s] += e;
                            tt[s] = fmaf(e, d, tt[s]);
                            if (d2 < tv2[s]) {              // constant-index insert tree
                                if (d2 < tv1[s]) {
                                    tv2[s] = tv1[s]; ti2[s] = ti1[s];
                                    if (d2 < tv0[s]) {
                                        tv1[s] = tv0[s]; ti1[s] = ti0[s];
                                        tv0[s] = d2; ti0[s] = code;
                                    } else { tv1[s] = d2; ti1[s] = code; }
                                } else { tv2[s] = d2; ti2[s] = code; }
                            }
                        }
        }

        buf = (buf == 2) ? 0 : buf + 1;
        pbuf = (pbuf == 2) ? 0 : pbuf + 1;
    }

    // ---- merge 8 warp-partials per row via smem (record = 8 words)
    __syncthreads();
    float* msm = (float*)(sm + A_BYTES);
    int*   mim = (int*)msm;
    const int REC = 8;
#pragma unroll
    for (int s = 0; s < 4; ++s) {
        int row_local = wm * 32 + (s >> 1) * 16 + (lane >> 2) + (s & 1) * 8;
        int base = (row_local * 8 + wn * 4 + (lane & 3)) * REC;
        msm[base + 0] = ss[s]; msm[base + 1] = tt[s];
        msm[base + 2] = tv0[s]; msm[base + 3] = tv1[s]; msm[base + 4] = tv2[s];
        mim[base + 5] = ti0[s]; mim[base + 6] = ti1[s]; mim[base + 7] = ti2[s];
    }
    __syncthreads();
    if (tid < 128) {
        int row = tid;
        float S = 0.f, T = 0.f;
        float bv0 = 1e30f, bv1 = 1e30f, bv2 = 1e30f;
        int bi0 = 0, bi1 = 0, bi2 = 0;
#pragma unroll
        for (int j = 0; j < 8; ++j) {
            int base = (row * 8 + j) * REC;
            S += msm[base + 0];
            T += msm[base + 1];
#pragma unroll
            for (int k = 0; k < 3; ++k) {
                float v = msm[base + 2 + k];
                int   ix = mim[base + 5 + k];
                if (v < bv2) {
                    if (v < bv1) {
                        bv2 = bv1; bi2 = bi1;
                        if (v < bv0) { bv1 = bv0; bi1 = bi0; bv0 = v; bi0 = ix; }
                        else         { bv1 = v;  bi1 = ix; }
                    } else { bv2 = v; bi2 = ix; }
                }
            }
        }
        int gp = kq * NTOK + n0 + row;
        g_ps[gp] = S; g_pt[gp] = T;
        g_pv0[gp] = bv0; g_pv1[gp] = bv1; g_pv2[gp] = bv2;
        g_pi0[gp] = bi0; g_pi1[gp] = bi1; g_pi2[gp] = bi2;
    }
}

// ---------------- merge + exact rescore (early-exit) + outputs ----------------
__global__ void mergeout_kernel(const float* __restrict__ z, const float* __restrict__ cb,
                                const float* __restrict__ yb, const float* __restrict__ et,
                                float* __restrict__ out, int N) {
    int warp = (blockIdx.x * blockDim.x + threadIdx.x) >> 5;
    int lane = threadIdx.x & 31;
    if (warp >= N) return;

    float S = 0.f, T = 0.f;
    float bv0 = 1e30f, bv1 = 1e30f, bv2 = 1e30f, bv3 = 1e30f;
    int bi0 = 0, bi1 = 0, bi2 = 0, bi3 = 0;
#pragma unroll
    for (int j = 0; j < KQ; ++j) {
        int gp = j * NTOK + warp;
        S += g_ps[gp];
        T += g_pt[gp];
        float vs[3] = {g_pv0[gp], g_pv1[gp], g_pv2[gp]};
        int   is[3] = {g_pi0[gp], g_pi1[gp], g_pi2[gp]};
#pragma unroll
        for (int k = 0; k < 3; ++k) {
            float v = vs[k]; int ix = is[k];
            if (v < bv3) {                                 // constant-index top-4 tree
                if (v < bv1) {
                    bv3 = bv2; bi3 = bi2;
                    bv2 = bv1; bi2 = bi1;
                    if (v < bv0) { bv1 = bv0; bi1 = bi0; bv0 = v; bi0 = ix; }
                    else         { bv1 = v;  bi1 = ix; }
                } else {
                    if (v < bv2) { bv3 = bv2; bi3 = bi2; bv2 = v; bi2 = ix; }
                    else         { bv3 = v;  bi3 = ix; }
                }
            }
        }
    }

    float4 zv[4];
    const float4* zr = (const float4*)(z + (size_t)warp * D);
#pragma unroll
    for (int i = 0; i < 4; ++i) zv[i] = zr[lane + i * 32];
    float zsq = g_zsq[warp];

    // exact rescore with early exit: noisy d2 error sigma ~0.06, cut at 8 sigma
    float cut = bv0 + 0.5f;
    int cand[4] = {bi0, bi1, bi2, bi3};
    float cnv[4] = {bv0, bv1, bv2, bv3};
    float best = 1e30f; int bidx = 0x7fffffff;
#pragma unroll
    for (int c = 0; c < 4; ++c) {
        if (c > 0 && cnv[c] > cut) break;      // warp-uniform (sorted)
        int idx = cand[c];
        const float4* cr = (const float4*)(cb + (size_t)idx * D);
        float dot = 0.f;
#pragma unroll
        for (int i = 0; i < 4; ++i) {
            float4 cv = cr[lane + i * 32];
            dot += zv[i].x * cv.x + zv[i].y * cv.y + zv[i].z * cv.z + zv[i].w * cv.w;
        }
#pragma unroll
        for (int off = 16; off; off >>= 1) dot += __shfl_xor_sync(0xffffffffu, dot, off);
        float d2 = fmaxf(zsq + g_csq[idx] - 2.f * dot, 0.f);
        if (d2 < best || (d2 == best && idx < bidx)) { best = d2; bidx = idx; }
    }

    // winner row is L1-hot from the rescore loop: write quantized + deviation
    const float4* crow = (const float4*)(cb + (size_t)bidx * D);
    const float4* yrow = (const float4*)(yb + (size_t)warp * D);
    float4*       qrow = (float4*)(out + (size_t)warp * D);
    float dacc = 0.f;
#pragma unroll
    for (int i = 0; i < 4; ++i) {
        float4 cv = crow[lane + i * 32];
        float4 yv = yrow[lane + i * 32];
        qrow[lane + i * 32] = cv;
        float dx = cv.x - yv.x, dy = cv.y - yv.y, dz = cv.z - yv.z, dw = cv.w - yv.w;
        dacc += dx * dx + dy * dy + dz * dz + dw * dw;
    }
#pragma unroll
    for (int off = 16; off; off >>= 1) dacc += __shfl_down_sync(0xffffffffu, dacc, off);
    if (lane == 0) {
        g_dmin[warp] = sqrtf(best);
        g_H[warp]    = __logf(S) + T / S;     // max-free identity
        float dev = sqrtf(dacc);
        out[(size_t)N * D + N + warp] = et[warp] + (dev > 0.01f ? 1.0f : 0.0f);
    }
}

// ---------------- loss stage 1: parallel slice reduction ----------------
__global__ void loss_reduce(int N) {
    __shared__ float sd[256], sh[256];
    int t = threadIdx.x;
    int per = N / LR_BLOCKS;                  // 512 rows per block
    int base = blockIdx.x * per;
    float a = 0.f, b = 0.f;
    const float4* pd = (const float4*)(g_dmin + base);
    const float4* ph = (const float4*)(g_H + base);
    for (int i = t; i < per / 4; i += 256) {
        float4 vd = pd[i], vh = ph[i];
        a += vd.x + vd.y + vd.z + vd.w;
        b += vh.x + vh.y + vh.z + vh.w;
    }
    sd[t] = a; sh[t] = b;
    __syncthreads();
    for (int off = 128; off; off >>= 1) {
        if (t < off) { sd[t] += sd[t + off]; sh[t] += sh[t + off]; }
        __syncthreads();
    }
    if (t == 0) { g_pr[blockIdx.x] = sd[0]; g_phh[blockIdx.x] = sh[0]; }
}

// ---------------- loss stage 2: deterministic finalize + parallel broadcast ----------------
__global__ void loss_bcast(float* __restrict__ out, int N) {
    float a = 0.f, b = 0.f;
#pragma unroll
    for (int i = 0; i < LR_BLOCKS; ++i) { a += g_pr[i]; b += g_phh[i]; }
    float loss = a / (float)N + 0.1f * b / (float)N;
    int idx = blockIdx.x * blockDim.x + threadIdx.x;
    if (idx < N) out[(size_t)N * D + idx] = loss;
}

extern "C" void kernel_launch(void* const* d_in, const int* in_sizes, int n_in,
                              void* d_out, int out_size) {
    const float* z  = (const float*)d_in[0];
    const float* yb = (const float*)d_in[1];
    const float* et = (const float*)d_in[2];
    const float* cb = (const float*)d_in[3];
    int N = in_sizes[0] / D;
    int K = in_sizes[3] / D;
    float* out = (float*)d_out;

    cudaFuncSetAttribute(gemm_kernel, cudaFuncAttributeMaxDynamicSharedMemorySize, SMEM_SZ);

    split_kernel<<<(N + K + 7) / 8, 256>>>(z, cb, N, K);
    gemm_kernel<<<256 * KQ, 256, SMEM_SZ>>>();
    mergeout_kernel<<<(N + 7) / 8, 256>>>(z, cb, yb, et, out, N);
    loss_reduce<<<LR_BLOCKS, 256>>>(N);
    loss_bcast<<<(N + 255) / 256, 256>>>(out, N);
}